// round 5
// baseline (speedup 1.0000x reference)
#include <cuda_runtime.h>

#define BB 4
#define LL 2048
#define DD 1024
#define NH 16
#define HDIM 64
#define QKVN (NH * HDIM * 3)   // 3072
#define NROWS (BB * LL)        // 8192

// ---- scratch (static device globals; no dynamic allocation) ----
__device__ float g_qkv[(size_t)NROWS * QKVN];          // 96 MB
__device__ float g_newv[(size_t)NROWS * (NH * HDIM)];  // 32 MB
__device__ float g_hbuf[(size_t)NROWS * DD];           // 32 MB

__device__ __forceinline__ float swish_f(float v) {
    return v * (1.0f / (1.0f + __expf(-v)));
}

// ============================================================================
// SGEMM 128x128x8, 256 threads, 8x8 per thread.
// EPI=0: C = swish(A*B + bias)
// EPI=1: C = skip + swish(A*B + bias)
// ============================================================================
template <int EPI>
__global__ void __launch_bounds__(256, 2)
sgemm_kernel(const float* __restrict__ A, const float* __restrict__ Bm,
             const float* __restrict__ bias, const float* __restrict__ skip,
             float* __restrict__ C, int M, int N, int K)
{
    __shared__ float As[8][128];   // As[k][m]
    __shared__ float Bs[8][128];   // Bs[k][n]

    const int tid = threadIdx.x;
    const int bm = blockIdx.y, bn = blockIdx.x;
    const int arow = tid >> 1;            // 0..127
    const int acol = (tid & 1) << 2;      // 0 or 4
    const int brow = tid >> 5;            // 0..7
    const int bcol = (tid & 31) << 2;     // 0..124
    const int ty = tid >> 4, tx = tid & 15;

    const float* Ap = A + (size_t)(bm * 128 + arow) * K + acol;
    const float* Bp = Bm + (size_t)brow * N + bn * 128 + bcol;

    float acc[8][8] = {};

    for (int k0 = 0; k0 < K; k0 += 8) {
        float4 av = *(const float4*)(Ap + k0);
        float4 bv = *(const float4*)(Bp + (size_t)k0 * N);
        As[acol + 0][arow] = av.x;
        As[acol + 1][arow] = av.y;
        As[acol + 2][arow] = av.z;
        As[acol + 3][arow] = av.w;
        *(float4*)(&Bs[brow][bcol]) = bv;
        __syncthreads();

        #pragma unroll
        for (int kk = 0; kk < 8; kk++) {
            float ar[8], br[8];
            *(float4*)&ar[0] = *(const float4*)&As[kk][ty * 8];
            *(float4*)&ar[4] = *(const float4*)&As[kk][ty * 8 + 4];
            *(float4*)&br[0] = *(const float4*)&Bs[kk][tx * 8];
            *(float4*)&br[4] = *(const float4*)&Bs[kk][tx * 8 + 4];
            #pragma unroll
            for (int i = 0; i < 8; i++)
                #pragma unroll
                for (int j = 0; j < 8; j++)
                    acc[i][j] = fmaf(ar[i], br[j], acc[i][j]);
        }
        __syncthreads();
    }

    // epilogue
    #pragma unroll
    for (int i = 0; i < 8; i++) {
        const size_t row = (size_t)bm * 128 + ty * 8 + i;
        #pragma unroll
        for (int j = 0; j < 8; j += 4) {
            const int col = bn * 128 + tx * 8 + j;
            float vv[4];
            #pragma unroll
            for (int jj = 0; jj < 4; jj++) {
                float v = acc[i][j + jj] + bias[col + jj];
                float sw = swish_f(v);
                if (EPI == 1) sw += skip[row * (size_t)N + col + jj];
                vv[jj] = sw;
            }
            *(float4*)&C[row * (size_t)N + col] =
                make_float4(vv[0], vv[1], vv[2], vv[3]);
        }
    }
}

// ============================================================================
// Flash attention, fp32. One block = (b, h, 64-query tile). 256 threads.
// Q,K stored transposed in smem (d-major, pad 65). S tile in smem (pad 65).
// Online softmax with running max/sum. scale = 1/sqrt(L) folded into Q.
// ============================================================================
#define SM_QST 0
#define SM_KST 4160
#define SM_VS  8320
#define SM_SS  12416
#define SM_M   16576
#define SM_L   16640
#define SM_A   16704
#define SM_FLOATS 16768   // 67072 bytes

__global__ void __launch_bounds__(256, 2)
attn_kernel(const float* __restrict__ qkv, float* __restrict__ nv)
{
    extern __shared__ float sm[];
    float* Qst = sm + SM_QST;   // [64][65], Qst[d*65 + r]
    float* Kst = sm + SM_KST;   // [64][65], Kst[d*65 + c]
    float* Vs  = sm + SM_VS;    // [64][64], Vs[k*64 + d]
    float* Ss  = sm + SM_SS;    // [64][65], Ss[r*65 + c]
    float* m_s = sm + SM_M;
    float* l_s = sm + SM_L;
    float* a_s = sm + SM_A;

    const int qt = blockIdx.x, h = blockIdx.y, b = blockIdx.z;
    const int tid = threadIdx.x;
    const int ty = tid >> 4, tx = tid & 15;
    const int wid = tid >> 5, lane = tid & 31;
    const float scale = 0.022097086912079608f;  // 1/sqrt(2048)
    const size_t rowbase = (size_t)b * LL;
    const int hoff = h * (3 * HDIM);

    // load Q tile (transposed + scaled)
    #pragma unroll
    for (int it = 0; it < 4; it++) {
        int fid = it * 256 + tid;
        int r = fid >> 4;
        int c4 = (fid & 15) << 2;
        const float* p = qkv + (rowbase + qt * 64 + r) * QKVN + hoff + c4;
        float4 v = *(const float4*)p;
        Qst[(c4 + 0) * 65 + r] = v.x * scale;
        Qst[(c4 + 1) * 65 + r] = v.y * scale;
        Qst[(c4 + 2) * 65 + r] = v.z * scale;
        Qst[(c4 + 3) * 65 + r] = v.w * scale;
    }
    if (tid < 64) { m_s[tid] = -3.0e38f; l_s[tid] = 0.0f; }

    float o[4][4] = {};

    for (int kt = 0; kt < LL / 64; kt++) {
        // load K (transposed) and V tiles
        #pragma unroll
        for (int it = 0; it < 4; it++) {
            int fid = it * 256 + tid;
            int r = fid >> 4;
            int c4 = (fid & 15) << 2;
            const float* pk = qkv + (rowbase + kt * 64 + r) * QKVN + hoff + HDIM + c4;
            float4 kv = *(const float4*)pk;
            Kst[(c4 + 0) * 65 + r] = kv.x;
            Kst[(c4 + 1) * 65 + r] = kv.y;
            Kst[(c4 + 2) * 65 + r] = kv.z;
            Kst[(c4 + 3) * 65 + r] = kv.w;
            const float* pv = qkv + (rowbase + kt * 64 + r) * QKVN + hoff + 2 * HDIM + c4;
            *(float4*)&Vs[r * 64 + c4] = *(const float4*)pv;
        }
        __syncthreads();

        // S = Q K^T (64x64, each thread 4x4)
        float s[4][4] = {};
        #pragma unroll 8
        for (int k = 0; k < 64; k++) {
            float a0 = Qst[k * 65 + ty * 4 + 0];
            float a1 = Qst[k * 65 + ty * 4 + 1];
            float a2 = Qst[k * 65 + ty * 4 + 2];
            float a3 = Qst[k * 65 + ty * 4 + 3];
            float b0 = Kst[k * 65 + tx * 4 + 0];
            float b1 = Kst[k * 65 + tx * 4 + 1];
            float b2 = Kst[k * 65 + tx * 4 + 2];
            float b3 = Kst[k * 65 + tx * 4 + 3];
            s[0][0] = fmaf(a0, b0, s[0][0]); s[0][1] = fmaf(a0, b1, s[0][1]);
            s[0][2] = fmaf(a0, b2, s[0][2]); s[0][3] = fmaf(a0, b3, s[0][3]);
            s[1][0] = fmaf(a1, b0, s[1][0]); s[1][1] = fmaf(a1, b1, s[1][1]);
            s[1][2] = fmaf(a1, b2, s[1][2]); s[1][3] = fmaf(a1, b3, s[1][3]);
            s[2][0] = fmaf(a2, b0, s[2][0]); s[2][1] = fmaf(a2, b1, s[2][1]);
            s[2][2] = fmaf(a2, b2, s[2][2]); s[2][3] = fmaf(a2, b3, s[2][3]);
            s[3][0] = fmaf(a3, b0, s[3][0]); s[3][1] = fmaf(a3, b1, s[3][1]);
            s[3][2] = fmaf(a3, b2, s[3][2]); s[3][3] = fmaf(a3, b3, s[3][3]);
        }
        #pragma unroll
        for (int i = 0; i < 4; i++)
            #pragma unroll
            for (int j = 0; j < 4; j++)
                Ss[(ty * 4 + i) * 65 + tx * 4 + j] = s[i][j];
        __syncthreads();

        // online softmax: warp wid owns rows [wid*8, wid*8+8)
        #pragma unroll
        for (int rr = 0; rr < 8; rr++) {
            int row = wid * 8 + rr;
            float v0 = Ss[row * 65 + lane];
            float v1 = Ss[row * 65 + 32 + lane];
            float mx = fmaxf(v0, v1);
            #pragma unroll
            for (int off = 16; off > 0; off >>= 1)
                mx = fmaxf(mx, __shfl_xor_sync(0xffffffffu, mx, off));
            float mprev = m_s[row];
            float mnew = fmaxf(mprev, mx);
            float p0 = __expf(v0 - mnew);
            float p1 = __expf(v1 - mnew);
            Ss[row * 65 + lane] = p0;
            Ss[row * 65 + 32 + lane] = p1;
            float sum = p0 + p1;
            #pragma unroll
            for (int off = 16; off > 0; off >>= 1)
                sum += __shfl_xor_sync(0xffffffffu, sum, off);
            if (lane == 0) {
                float alpha = __expf(mprev - mnew);
                l_s[row] = l_s[row] * alpha + sum;
                m_s[row] = mnew;
                a_s[row] = alpha;
            }
        }
        __syncthreads();

        // rescale O, accumulate O += P V
        {
            float al0 = a_s[ty * 4 + 0], al1 = a_s[ty * 4 + 1];
            float al2 = a_s[ty * 4 + 2], al3 = a_s[ty * 4 + 3];
            #pragma unroll
            for (int j = 0; j < 4; j++) {
                o[0][j] *= al0; o[1][j] *= al1; o[2][j] *= al2; o[3][j] *= al3;
            }
        }
        #pragma unroll 8
        for (int k = 0; k < 64; k++) {
            float a0 = Ss[(ty * 4 + 0) * 65 + k];
            float a1 = Ss[(ty * 4 + 1) * 65 + k];
            float a2 = Ss[(ty * 4 + 2) * 65 + k];
            float a3 = Ss[(ty * 4 + 3) * 65 + k];
            float4 bv = *(const float4*)&Vs[k * 64 + tx * 4];
            o[0][0] = fmaf(a0, bv.x, o[0][0]); o[0][1] = fmaf(a0, bv.y, o[0][1]);
            o[0][2] = fmaf(a0, bv.z, o[0][2]); o[0][3] = fmaf(a0, bv.w, o[0][3]);
            o[1][0] = fmaf(a1, bv.x, o[1][0]); o[1][1] = fmaf(a1, bv.y, o[1][1]);
            o[1][2] = fmaf(a1, bv.z, o[1][2]); o[1][3] = fmaf(a1, bv.w, o[1][3]);
            o[2][0] = fmaf(a2, bv.x, o[2][0]); o[2][1] = fmaf(a2, bv.y, o[2][1]);
            o[2][2] = fmaf(a2, bv.z, o[2][2]); o[2][3] = fmaf(a2, bv.w, o[2][3]);
            o[3][0] = fmaf(a3, bv.x, o[3][0]); o[3][1] = fmaf(a3, bv.y, o[3][1]);
            o[3][2] = fmaf(a3, bv.z, o[3][2]); o[3][3] = fmaf(a3, bv.w, o[3][3]);
        }
        __syncthreads();
    }

    // final normalize + write
    #pragma unroll
    for (int i = 0; i < 4; i++) {
        const size_t row = rowbase + qt * 64 + ty * 4 + i;
        const float li = 1.0f / l_s[ty * 4 + i];
        float4 ov = make_float4(o[i][0] * li, o[i][1] * li, o[i][2] * li, o[i][3] * li);
        *(float4*)&nv[row * (size_t)(NH * HDIM) + h * HDIM + tx * 4] = ov;
    }
}

// ============================================================================
// LayerNorm over D=1024. One block (256 threads) per row, 1 float4/thread.
// ============================================================================
__global__ void __launch_bounds__(256)
ln_kernel(const float* __restrict__ hb, float* __restrict__ out)
{
    const int row = blockIdx.x;
    const float4* p4 = (const float4*)(hb + (size_t)row * DD);
    float4 v = p4[threadIdx.x];
    float s  = v.x + v.y + v.z + v.w;
    float s2 = v.x * v.x + v.y * v.y + v.z * v.z + v.w * v.w;

    __shared__ float rs[8], rs2[8];
    const int wid = threadIdx.x >> 5, lane = threadIdx.x & 31;
    #pragma unroll
    for (int off = 16; off > 0; off >>= 1) {
        s  += __shfl_xor_sync(0xffffffffu, s, off);
        s2 += __shfl_xor_sync(0xffffffffu, s2, off);
    }
    if (lane == 0) { rs[wid] = s; rs2[wid] = s2; }
    __syncthreads();
    if (threadIdx.x == 0) {
        float a = 0.f, b2 = 0.f;
        #pragma unroll
        for (int i = 0; i < 8; i++) { a += rs[i]; b2 += rs2[i]; }
        rs[0] = a; rs2[0] = b2;
    }
    __syncthreads();
    const float mu = rs[0] * (1.0f / DD);
    const float var = rs2[0] * (1.0f / DD) - mu * mu;
    const float rstd = rsqrtf(var + 1e-5f);
    float4 ov = make_float4((v.x - mu) * rstd, (v.y - mu) * rstd,
                            (v.z - mu) * rstd, (v.w - mu) * rstd);
    ((float4*)(out + (size_t)row * DD))[threadIdx.x] = ov;
}

// ============================================================================
extern "C" void kernel_launch(void* const* d_in, const int* in_sizes, int n_in,
                              void* d_out, int out_size)
{
    const float* x     = (const float*)d_in[0];
    const float* W_fc  = (const float*)d_in[1];
    const float* b_fc  = (const float*)d_in[2];
    const float* W_fc2 = (const float*)d_in[3];
    const float* b_fc2 = (const float*)d_in[4];
    float* out = (float*)d_out;

    void* p;
    cudaGetSymbolAddress(&p, g_qkv);  float* qkv = (float*)p;
    cudaGetSymbolAddress(&p, g_newv); float* nv  = (float*)p;
    cudaGetSymbolAddress(&p, g_hbuf); float* hb  = (float*)p;

    // GEMM1: qkv = swish(x @ W_fc + b_fc)   [8192,1024]x[1024,3072]
    dim3 g1(QKVN / 128, NROWS / 128);
    sgemm_kernel<0><<<g1, 256>>>(x, W_fc, b_fc, nullptr, qkv, NROWS, QKVN, DD);

    // Attention: nv = softmax(q k^T / sqrt(L)) v
    const int smem_bytes = SM_FLOATS * 4;
    cudaFuncSetAttribute(attn_kernel,
                         cudaFuncAttributeMaxDynamicSharedMemorySize, smem_bytes);
    dim3 ga(LL / 64, NH, BB);
    attn_kernel<<<ga, 256, smem_bytes>>>(qkv, nv);

    // GEMM2: hb = x + swish(nv @ W_fc2 + b_fc2)
    dim3 g2(DD / 128, NROWS / 128);
    sgemm_kernel<1><<<g2, 256>>>(nv, W_fc2, b_fc2, x, hb, NROWS, DD, DD);

    // LayerNorm -> out
    ln_kernel<<<NROWS, 256>>>(hb, out);
}

// round 9
// speedup vs baseline: 2.7562x; 2.7562x over previous
#include <cuda_runtime.h>

#define BB 4
#define LL 2048
#define DD 1024
#define NH 16
#define HDIM 64
#define QKVN (NH * HDIM * 3)   // 3072
#define NROWS (BB * LL)        // 8192

// ---- scratch (static device globals; no dynamic allocation) ----
__device__ float g_qkv[(size_t)NROWS * QKVN];          // 96 MB
__device__ float g_newv[(size_t)NROWS * (NH * HDIM)];  // 32 MB
__device__ float g_hbuf[(size_t)NROWS * DD];           // 32 MB
__device__ float g_xr[(size_t)NROWS * DD];             // 32 MB (x rounded to tf32)
__device__ float g_wfcr[(size_t)DD * QKVN];            // 12 MB
__device__ float g_wfc2r[(size_t)(NH * HDIM) * DD];    //  4 MB

__device__ __forceinline__ float swish_f(float v) {
    return v * (1.0f / (1.0f + __expf(-v)));
}

__device__ __forceinline__ float rna_tf32(float x) {
    unsigned u;
    asm("cvt.rna.tf32.f32 %0, %1;" : "=r"(u) : "f"(x));
    return __uint_as_float(u);
}

__device__ __forceinline__ unsigned asu(float x) { return __float_as_uint(x); }

__device__ __forceinline__ void cp16(float* dst, const float* src) {
    unsigned s = (unsigned)__cvta_generic_to_shared(dst);
    asm volatile("cp.async.cg.shared.global [%0], [%1], 16;\n" :: "r"(s), "l"(src));
}
#define CP_COMMIT() asm volatile("cp.async.commit_group;\n")

// m16n8k8 tf32 mma, accumulate in place.
__device__ __forceinline__ void mma_tf32(float c[4], const unsigned a[4],
                                         const unsigned b[2]) {
    asm volatile(
        "mma.sync.aligned.m16n8k8.row.col.f32.tf32.tf32.f32 "
        "{%0,%1,%2,%3}, {%4,%5,%6,%7}, {%8,%9}, {%0,%1,%2,%3};\n"
        : "+f"(c[0]), "+f"(c[1]), "+f"(c[2]), "+f"(c[3])
        : "r"(a[0]), "r"(a[1]), "r"(a[2]), "r"(a[3]), "r"(b[0]), "r"(b[1]));
}

// ============================================================================
// Elementwise round-to-tf32 (rna) pass.
// ============================================================================
__global__ void __launch_bounds__(256)
round_kernel(const float* __restrict__ in, float* __restrict__ out, int n4)
{
    int i = blockIdx.x * blockDim.x + threadIdx.x;
    if (i < n4) {
        float4 v = ((const float4*)in)[i];
        v.x = rna_tf32(v.x); v.y = rna_tf32(v.y);
        v.z = rna_tf32(v.z); v.w = rna_tf32(v.w);
        ((float4*)out)[i] = v;
    }
}

// ============================================================================
// TF32 tensor-core GEMM: block 128x128, ktile 32, 256 threads (8 warps 2x4,
// warp tile 64x32). Double-buffered cp.async. A,B must be pre-rounded tf32.
// EPI=0: C = rna(swish(A*B + bias))
// EPI=1: C = skip + swish(A*B + bias)
// smem: As[2][128][36], Bs[2][32][136]
// ============================================================================
#define GA_STRIDE 36
#define GB_STRIDE 136
#define GA_BUF (128 * GA_STRIDE)   // 4608
#define GB_BUF (32 * GB_STRIDE)    // 4352
#define G_SMEM_FLOATS (2 * GA_BUF + 2 * GB_BUF)  // 17920 -> 71680 B

template <int EPI>
__global__ void __launch_bounds__(256, 2)
gemm_tc(const float* __restrict__ A, const float* __restrict__ Bm,
        const float* __restrict__ bias, const float* __restrict__ skip,
        float* __restrict__ C, int M, int N, int K)
{
    extern __shared__ float sm[];
    float* As = sm;                 // [2][128][36]
    float* Bs = sm + 2 * GA_BUF;    // [2][32][136]

    const int tid = threadIdx.x;
    const int bm = blockIdx.y, bn = blockIdx.x;
    const int wid = tid >> 5, lane = tid & 31;
    const int wm = wid >> 2, wn = wid & 3;  // warp 64x32 tile
    const int lg = lane >> 2, lc = lane & 3;

    const float* Ag = A + (size_t)bm * 128 * K;
    const float* Bg = Bm + bn * 128;
    const int T = K / 32;

    // prologue: tile 0
    #pragma unroll
    for (int it = 0; it < 4; it++) {
        int fid = it * 256 + tid;
        int r = fid >> 3, c4 = fid & 7;
        cp16(&As[r * GA_STRIDE + c4 * 4], Ag + (size_t)r * K + c4 * 4);
    }
    #pragma unroll
    for (int it = 0; it < 4; it++) {
        int fid = it * 256 + tid;
        int r = fid >> 5, c4 = fid & 31;
        cp16(&Bs[r * GB_STRIDE + c4 * 4], Bg + (size_t)r * N + c4 * 4);
    }
    CP_COMMIT();

    float acc[4][4][4] = {};

    for (int t = 0; t < T; t++) {
        const int cur = t & 1;
        if (t + 1 < T) {
            const int nb = cur ^ 1;
            const int k0 = (t + 1) * 32;
            #pragma unroll
            for (int it = 0; it < 4; it++) {
                int fid = it * 256 + tid;
                int r = fid >> 3, c4 = fid & 7;
                cp16(&As[nb * GA_BUF + r * GA_STRIDE + c4 * 4],
                     Ag + (size_t)r * K + k0 + c4 * 4);
            }
            #pragma unroll
            for (int it = 0; it < 4; it++) {
                int fid = it * 256 + tid;
                int r = fid >> 5, c4 = fid & 31;
                cp16(&Bs[nb * GB_BUF + r * GB_STRIDE + c4 * 4],
                     Bg + (size_t)(k0 + r) * N + c4 * 4);
            }
            CP_COMMIT();
            asm volatile("cp.async.wait_group 1;\n");
        } else {
            asm volatile("cp.async.wait_group 0;\n");
        }
        __syncthreads();

        const float* Ab = As + cur * GA_BUF;
        const float* Bb = Bs + cur * GB_BUF;

        #pragma unroll
        for (int ks = 0; ks < 4; ks++) {
            const int kA = ks * 8 + lc;
            unsigned a[4][4], b[4][2];
            #pragma unroll
            for (int mf = 0; mf < 4; mf++) {
                int m = wm * 64 + mf * 16 + lg;
                a[mf][0] = asu(Ab[m * GA_STRIDE + kA]);
                a[mf][1] = asu(Ab[(m + 8) * GA_STRIDE + kA]);
                a[mf][2] = asu(Ab[m * GA_STRIDE + kA + 4]);
                a[mf][3] = asu(Ab[(m + 8) * GA_STRIDE + kA + 4]);
            }
            #pragma unroll
            for (int nf = 0; nf < 4; nf++) {
                int n = wn * 32 + nf * 8 + lg;
                b[nf][0] = asu(Bb[kA * GB_STRIDE + n]);
                b[nf][1] = asu(Bb[(kA + 4) * GB_STRIDE + n]);
            }
            #pragma unroll
            for (int mf = 0; mf < 4; mf++)
                #pragma unroll
                for (int nf = 0; nf < 4; nf++)
                    mma_tf32(acc[mf][nf], a[mf], b[nf]);
        }
        __syncthreads();
    }

    // epilogue
    #pragma unroll
    for (int mf = 0; mf < 4; mf++) {
        const size_t r0 = (size_t)bm * 128 + wm * 64 + mf * 16 + lg;
        #pragma unroll
        for (int nf = 0; nf < 4; nf++) {
            const int c = bn * 128 + wn * 32 + nf * 8 + lc * 2;
            const float b0 = bias[c], b1 = bias[c + 1];
            float v00 = swish_f(acc[mf][nf][0] + b0);
            float v01 = swish_f(acc[mf][nf][1] + b1);
            float v10 = swish_f(acc[mf][nf][2] + b0);
            float v11 = swish_f(acc[mf][nf][3] + b1);
            if (EPI == 1) {
                v00 += skip[r0 * (size_t)N + c];
                v01 += skip[r0 * (size_t)N + c + 1];
                v10 += skip[(r0 + 8) * (size_t)N + c];
                v11 += skip[(r0 + 8) * (size_t)N + c + 1];
            } else {
                v00 = rna_tf32(v00); v01 = rna_tf32(v01);
                v10 = rna_tf32(v10); v11 = rna_tf32(v11);
            }
            *(float2*)&C[r0 * (size_t)N + c] = make_float2(v00, v01);
            *(float2*)&C[(r0 + 8) * (size_t)N + c] = make_float2(v10, v11);
        }
    }
}

// ============================================================================
// TF32 tensor-core flash attention. Block = (qt, h, b); 64-row Q tile;
// 8 warps (4 m-bands x 2 n-bands), warp tile 16x32.
// smem floats: Qs[64][68], Ks[2][64][68], Vs[2][64][72], Ss[64][68], stats.
// ============================================================================
#define AQ_S 68
#define AK_S 68
#define AV_S 72
#define AS_S 68
#define A_QS   0
#define A_KS   4352
#define A_KBUF 4352
#define A_VS   13056
#define A_VBUF 4608
#define A_SS   22272
#define A_M    26624
#define A_L    26688
#define A_A    26752
#define A_SMEM_FLOATS 26816   // 107264 B

__global__ void __launch_bounds__(256, 2)
attn_tc(const float* __restrict__ qkv, float* __restrict__ nv)
{
    extern __shared__ float sm[];
    float* Qs = sm + A_QS;
    float* Ks = sm + A_KS;
    float* Vs = sm + A_VS;
    float* Ss = sm + A_SS;
    float* m_s = sm + A_M;
    float* l_s = sm + A_L;
    float* a_s = sm + A_A;

    const int qt = blockIdx.x, h = blockIdx.y, b = blockIdx.z;
    const int tid = threadIdx.x, wid = tid >> 5, lane = tid & 31;
    const int wm = wid & 3, wn = wid >> 2;
    const int lg = lane >> 2, lc = lane & 3;
    const size_t rowbase = (size_t)b * LL;
    const int hoff = h * (3 * HDIM);
    const float scale = 0.022097086912079608f;  // 1/sqrt(2048)

    const float* kbase = qkv + rowbase * QKVN + hoff + HDIM;
    const float* vbase = qkv + rowbase * QKVN + hoff + 2 * HDIM;

    // prologue: K/V tile 0 via cp.async
    #pragma unroll
    for (int it = 0; it < 4; it++) {
        int fid = it * 256 + tid;
        int r = fid >> 4, c4 = fid & 15;
        cp16(&Ks[r * AK_S + c4 * 4], kbase + (size_t)r * QKVN + c4 * 4);
        cp16(&Vs[r * AV_S + c4 * 4], vbase + (size_t)r * QKVN + c4 * 4);
    }
    CP_COMMIT();

    // Q tile (scaled + rounded to tf32)
    #pragma unroll
    for (int it = 0; it < 4; it++) {
        int fid = it * 256 + tid;
        int r = fid >> 4, c4 = fid & 15;
        const float* p = qkv + (rowbase + qt * 64 + r) * QKVN + hoff + c4 * 4;
        float4 v = *(const float4*)p;
        float* q = &Qs[r * AQ_S + c4 * 4];
        q[0] = rna_tf32(v.x * scale); q[1] = rna_tf32(v.y * scale);
        q[2] = rna_tf32(v.z * scale); q[3] = rna_tf32(v.w * scale);
    }
    if (tid < 64) { m_s[tid] = -3.0e38f; l_s[tid] = 0.0f; }
    __syncthreads();

    // hoist Q fragments (constant across all key tiles)
    unsigned qa[8][4];
    {
        const int m = wm * 16 + lg;
        #pragma unroll
        for (int ks = 0; ks < 8; ks++) {
            const int k = ks * 8 + lc;
            qa[ks][0] = asu(Qs[m * AQ_S + k]);
            qa[ks][1] = asu(Qs[(m + 8) * AQ_S + k]);
            qa[ks][2] = asu(Qs[m * AQ_S + k + 4]);
            qa[ks][3] = asu(Qs[(m + 8) * AQ_S + k + 4]);
        }
    }

    float o[4][4] = {};

    for (int kt = 0; kt < LL / 64; kt++) {
        const int cur = kt & 1;
        if (kt + 1 < LL / 64) {
            const int nb = cur ^ 1;
            const float* kg = kbase + (size_t)(kt + 1) * 64 * QKVN;
            const float* vg = vbase + (size_t)(kt + 1) * 64 * QKVN;
            #pragma unroll
            for (int it = 0; it < 4; it++) {
                int fid = it * 256 + tid;
                int r = fid >> 4, c4 = fid & 15;
                cp16(&Ks[nb * A_KBUF + r * AK_S + c4 * 4], kg + (size_t)r * QKVN + c4 * 4);
                cp16(&Vs[nb * A_VBUF + r * AV_S + c4 * 4], vg + (size_t)r * QKVN + c4 * 4);
            }
            CP_COMMIT();
            asm volatile("cp.async.wait_group 1;\n");
        } else {
            asm volatile("cp.async.wait_group 0;\n");
        }
        __syncthreads();

        const float* Kb = Ks + cur * A_KBUF;
        const float* Vb = Vs + cur * A_VBUF;

        // S = Q K^T (warp: 16x32 of the 64x64 tile)
        float sacc[4][4] = {};
        #pragma unroll
        for (int ks = 0; ks < 8; ks++) {
            const int k = ks * 8 + lc;
            unsigned kb[4][2];
            #pragma unroll
            for (int nf = 0; nf < 4; nf++) {
                int n = wn * 32 + nf * 8 + lg;
                kb[nf][0] = asu(Kb[n * AK_S + k]);
                kb[nf][1] = asu(Kb[n * AK_S + k + 4]);
            }
            #pragma unroll
            for (int nf = 0; nf < 4; nf++)
                mma_tf32(sacc[nf], qa[ks], kb[nf]);
        }
        {
            const int r = wm * 16 + lg;
            #pragma unroll
            for (int nf = 0; nf < 4; nf++) {
                const int c = wn * 32 + nf * 8 + lc * 2;
                Ss[r * AS_S + c]       = sacc[nf][0];
                Ss[r * AS_S + c + 1]   = sacc[nf][1];
                Ss[(r + 8) * AS_S + c]     = sacc[nf][2];
                Ss[(r + 8) * AS_S + c + 1] = sacc[nf][3];
            }
        }
        __syncthreads();

        // online softmax: warp wid owns rows [wid*8, wid*8+8)
        #pragma unroll
        for (int rr = 0; rr < 8; rr++) {
            const int row = wid * 8 + rr;
            float v0 = Ss[row * AS_S + lane];
            float v1 = Ss[row * AS_S + 32 + lane];
            float mx = fmaxf(v0, v1);
            #pragma unroll
            for (int off = 16; off > 0; off >>= 1)
                mx = fmaxf(mx, __shfl_xor_sync(0xffffffffu, mx, off));
            const float mprev = m_s[row];
            const float mnew = fmaxf(mprev, mx);
            float p0 = __expf(v0 - mnew);
            float p1 = __expf(v1 - mnew);
            Ss[row * AS_S + lane] = rna_tf32(p0);
            Ss[row * AS_S + 32 + lane] = rna_tf32(p1);
            float sum = p0 + p1;
            #pragma unroll
            for (int off = 16; off > 0; off >>= 1)
                sum += __shfl_xor_sync(0xffffffffu, sum, off);
            if (lane == 0) {
                float alpha = __expf(mprev - mnew);
                l_s[row] = l_s[row] * alpha + sum;
                m_s[row] = mnew;
                a_s[row] = alpha;
            }
        }
        __syncthreads();

        // rescale O, then O += P V
        {
            const float al0 = a_s[wm * 16 + lg];
            const float al1 = a_s[wm * 16 + lg + 8];
            #pragma unroll
            for (int nf = 0; nf < 4; nf++) {
                o[nf][0] *= al0; o[nf][1] *= al0;
                o[nf][2] *= al1; o[nf][3] *= al1;
            }
        }
        #pragma unroll
        for (int ks = 0; ks < 8; ks++) {
            const int k = ks * 8 + lc;
            const int r = wm * 16 + lg;
            unsigned pa[4];
            pa[0] = asu(Ss[r * AS_S + k]);
            pa[1] = asu(Ss[(r + 8) * AS_S + k]);
            pa[2] = asu(Ss[r * AS_S + k + 4]);
            pa[3] = asu(Ss[(r + 8) * AS_S + k + 4]);
            #pragma unroll
            for (int nf = 0; nf < 4; nf++) {
                const int n = wn * 32 + nf * 8 + lg;
                unsigned vb[2];
                vb[0] = asu(Vb[k * AV_S + n]);
                vb[1] = asu(Vb[(k + 4) * AV_S + n]);
                mma_tf32(o[nf], pa, vb);
            }
        }
        __syncthreads();
    }

    // epilogue: 1/l scaling, round to tf32 (feeds GEMM2 A-operand), store
    {
        const int r = wm * 16 + lg;
        const float li0 = 1.0f / l_s[r];
        const float li1 = 1.0f / l_s[r + 8];
        const size_t row0 = rowbase + qt * 64 + r;
        #pragma unroll
        for (int nf = 0; nf < 4; nf++) {
            const int c = h * 64 + wn * 32 + nf * 8 + lc * 2;
            float2 v0 = make_float2(rna_tf32(o[nf][0] * li0), rna_tf32(o[nf][1] * li0));
            float2 v1 = make_float2(rna_tf32(o[nf][2] * li1), rna_tf32(o[nf][3] * li1));
            *(float2*)&nv[row0 * (size_t)(NH * HDIM) + c] = v0;
            *(float2*)&nv[(row0 + 8) * (size_t)(NH * HDIM) + c] = v1;
        }
    }
}

// ============================================================================
// LayerNorm over D=1024. One block (256 threads) per row.
// ============================================================================
__global__ void __launch_bounds__(256)
ln_kernel(const float* __restrict__ hb, float* __restrict__ out)
{
    const int row = blockIdx.x;
    const float4* p4 = (const float4*)(hb + (size_t)row * DD);
    float4 v = p4[threadIdx.x];
    float s  = v.x + v.y + v.z + v.w;
    float s2 = v.x * v.x + v.y * v.y + v.z * v.z + v.w * v.w;

    __shared__ float rs[8], rs2[8];
    const int wid = threadIdx.x >> 5, lane = threadIdx.x & 31;
    #pragma unroll
    for (int off = 16; off > 0; off >>= 1) {
        s  += __shfl_xor_sync(0xffffffffu, s, off);
        s2 += __shfl_xor_sync(0xffffffffu, s2, off);
    }
    if (lane == 0) { rs[wid] = s; rs2[wid] = s2; }
    __syncthreads();
    if (threadIdx.x == 0) {
        float a = 0.f, b2 = 0.f;
        #pragma unroll
        for (int i = 0; i < 8; i++) { a += rs[i]; b2 += rs2[i]; }
        rs[0] = a; rs2[0] = b2;
    }
    __syncthreads();
    const float mu = rs[0] * (1.0f / DD);
    const float var = rs2[0] * (1.0f / DD) - mu * mu;
    const float rstd = rsqrtf(var + 1e-5f);
    float4 ov = make_float4((v.x - mu) * rstd, (v.y - mu) * rstd,
                            (v.z - mu) * rstd, (v.w - mu) * rstd);
    ((float4*)(out + (size_t)row * DD))[threadIdx.x] = ov;
}

// ============================================================================
extern "C" void kernel_launch(void* const* d_in, const int* in_sizes, int n_in,
                              void* d_out, int out_size)
{
    const float* x     = (const float*)d_in[0];
    const float* W_fc  = (const float*)d_in[1];
    const float* b_fc  = (const float*)d_in[2];
    const float* W_fc2 = (const float*)d_in[3];
    const float* b_fc2 = (const float*)d_in[4];
    float* out = (float*)d_out;

    void* p;
    cudaGetSymbolAddress(&p, g_qkv);   float* qkv   = (float*)p;
    cudaGetSymbolAddress(&p, g_newv);  float* nv    = (float*)p;
    cudaGetSymbolAddress(&p, g_hbuf);  float* hb    = (float*)p;
    cudaGetSymbolAddress(&p, g_xr);    float* xr    = (float*)p;
    cudaGetSymbolAddress(&p, g_wfcr);  float* wfcr  = (float*)p;
    cudaGetSymbolAddress(&p, g_wfc2r); float* wfc2r = (float*)p;

    // Pre-round GEMM operands to tf32 (rna) so HW mma sees exact tf32 values.
    {
        int n4x = NROWS * DD / 4;            // 2097152
        int n4w = DD * QKVN / 4;             // 786432
        int n4w2 = NH * HDIM * DD / 4;       // 262144
        round_kernel<<<n4x / 256, 256>>>(x, xr, n4x);
        round_kernel<<<n4w / 256, 256>>>(W_fc, wfcr, n4w);
        round_kernel<<<n4w2 / 256, 256>>>(W_fc2, wfc2r, n4w2);
    }

    const int g_smem = G_SMEM_FLOATS * 4;    // 71680
    cudaFuncSetAttribute(gemm_tc<0>, cudaFuncAttributeMaxDynamicSharedMemorySize, g_smem);
    cudaFuncSetAttribute(gemm_tc<1>, cudaFuncAttributeMaxDynamicSharedMemorySize, g_smem);

    // GEMM1: qkv = rna(swish(x @ W_fc + b_fc))
    dim3 g1(QKVN / 128, NROWS / 128);
    gemm_tc<0><<<g1, 256, g_smem>>>(xr, wfcr, b_fc, nullptr, qkv, NROWS, QKVN, DD);

    // Attention
    const int a_smem = A_SMEM_FLOATS * 4;    // 107264
    cudaFuncSetAttribute(attn_tc, cudaFuncAttributeMaxDynamicSharedMemorySize, a_smem);
    dim3 ga(LL / 64, NH, BB);
    attn_tc<<<ga, 256, a_smem>>>(qkv, nv);

    // GEMM2: hb = x + swish(nv @ W_fc2 + b_fc2)
    dim3 g2(DD / 128, NROWS / 128);
    gemm_tc<1><<<g2, 256, g_smem>>>(nv, wfc2r, b_fc2, x, hb, NROWS, DD, DD);

    // LayerNorm -> out
    ln_kernel<<<NROWS, 256>>>(hb, out);
}

// round 10
// speedup vs baseline: 4.8617x; 1.7639x over previous
#include <cuda_runtime.h>
#include <cuda_bf16.h>

#define BB 4
#define LL 2048
#define DD 1024
#define NH 16
#define HDIM 64
#define QKVN (NH * HDIM * 3)   // 3072
#define NROWS (BB * LL)        // 8192

// ---- scratch (static device globals; no dynamic allocation) ----
__device__ float g_qkv[(size_t)NROWS * QKVN];          // 96 MB
__device__ float g_newv[(size_t)NROWS * (NH * HDIM)];  // 32 MB
__device__ float g_hbuf[(size_t)NROWS * DD];           // 32 MB
__device__ float g_xr[(size_t)NROWS * DD];             // 32 MB (x rounded to tf32)
__device__ float g_wfcr[(size_t)DD * QKVN];            // 12 MB
__device__ float g_wfc2r[(size_t)(NH * HDIM) * DD];    //  4 MB
__device__ __nv_bfloat16 g_vt[(size_t)BB * NH * HDIM * LL];  // 16 MB, V^T bf16 [b][h][d][seq]

__device__ __forceinline__ float swish_f(float v) {
    return v * (1.0f / (1.0f + __expf(-v)));
}

__device__ __forceinline__ float rna_tf32(float x) {
    unsigned u;
    asm("cvt.rna.tf32.f32 %0, %1;" : "=r"(u) : "f"(x));
    return __uint_as_float(u);
}

__device__ __forceinline__ unsigned asu(float x) { return __float_as_uint(x); }

__device__ __forceinline__ unsigned pack_bf16(float lo, float hi) {
    unsigned r;
    asm("cvt.rn.bf16x2.f32 %0, %1, %2;" : "=r"(r) : "f"(hi), "f"(lo));
    return r;
}

__device__ __forceinline__ void cp16(void* dst, const void* src) {
    unsigned s = (unsigned)__cvta_generic_to_shared(dst);
    asm volatile("cp.async.cg.shared.global [%0], [%1], 16;\n" :: "r"(s), "l"(src));
}
#define CP_COMMIT() asm volatile("cp.async.commit_group;\n")

// m16n8k8 tf32 mma, accumulate in place.
__device__ __forceinline__ void mma_tf32(float c[4], const unsigned a[4],
                                         const unsigned b[2]) {
    asm volatile(
        "mma.sync.aligned.m16n8k8.row.col.f32.tf32.tf32.f32 "
        "{%0,%1,%2,%3}, {%4,%5,%6,%7}, {%8,%9}, {%0,%1,%2,%3};\n"
        : "+f"(c[0]), "+f"(c[1]), "+f"(c[2]), "+f"(c[3])
        : "r"(a[0]), "r"(a[1]), "r"(a[2]), "r"(a[3]), "r"(b[0]), "r"(b[1]));
}

// m16n8k16 bf16 mma, accumulate in place.
__device__ __forceinline__ void mma_bf16(float c[4], const unsigned a[4],
                                         const unsigned b[2]) {
    asm volatile(
        "mma.sync.aligned.m16n8k16.row.col.f32.bf16.bf16.f32 "
        "{%0,%1,%2,%3}, {%4,%5,%6,%7}, {%8,%9}, {%0,%1,%2,%3};\n"
        : "+f"(c[0]), "+f"(c[1]), "+f"(c[2]), "+f"(c[3])
        : "r"(a[0]), "r"(a[1]), "r"(a[2]), "r"(a[3]), "r"(b[0]), "r"(b[1]));
}

// ============================================================================
// Elementwise round-to-tf32 (rna) pass.
// ============================================================================
__global__ void __launch_bounds__(256)
round_kernel(const float* __restrict__ in, float* __restrict__ out, int n4)
{
    int i = blockIdx.x * blockDim.x + threadIdx.x;
    if (i < n4) {
        float4 v = ((const float4*)in)[i];
        v.x = rna_tf32(v.x); v.y = rna_tf32(v.y);
        v.z = rna_tf32(v.z); v.w = rna_tf32(v.w);
        ((float4*)out)[i] = v;
    }
}

// ============================================================================
// V^T bf16 transpose: qkv V slice [seq][d] fp32 -> g_vt [b][h][d][seq] bf16.
// Grid (seqtile=32, h=16, b=4), 256 threads.
// ============================================================================
__global__ void __launch_bounds__(256)
vtrans_kernel(const float* __restrict__ qkv, __nv_bfloat16* __restrict__ vt)
{
    __shared__ float ts[64][65];
    const int st = blockIdx.x, h = blockIdx.y, b = blockIdx.z;
    const int tid = threadIdx.x;
    const float* src = qkv + ((size_t)b * LL + st * 64) * QKVN + h * (3 * HDIM) + 2 * HDIM;

    #pragma unroll
    for (int it = 0; it < 4; it++) {
        int fid = it * 256 + tid;
        int r = fid >> 4, c4 = (fid & 15) << 2;
        float4 v = *(const float4*)(src + (size_t)r * QKVN + c4);
        ts[r][c4] = v.x; ts[r][c4 + 1] = v.y; ts[r][c4 + 2] = v.z; ts[r][c4 + 3] = v.w;
    }
    __syncthreads();

    const size_t obase = ((size_t)(b * NH + h) * HDIM) * LL + st * 64;
    #pragma unroll
    for (int it = 0; it < 8; it++) {
        int fid = it * 256 + tid;
        int d = fid >> 5, j = fid & 31;
        unsigned pk = pack_bf16(ts[2 * j][d], ts[2 * j + 1][d]);
        *(unsigned*)((char*)vt + 2 * (obase + (size_t)d * LL + 2 * j)) = pk;
    }
}

// ============================================================================
// TF32 tensor-core GEMM: block 128x128, ktile 32, 256 threads (8 warps 2x4,
// warp tile 64x32). Double-buffered cp.async. A,B must be pre-rounded tf32.
// EPI=0: C = rna(swish(A*B + bias))
// EPI=1: C = skip + swish(A*B + bias)
// ============================================================================
#define GA_STRIDE 36
#define GB_STRIDE 136
#define GA_BUF (128 * GA_STRIDE)   // 4608
#define GB_BUF (32 * GB_STRIDE)    // 4352
#define G_SMEM_FLOATS (2 * GA_BUF + 2 * GB_BUF)  // 17920 -> 71680 B

template <int EPI>
__global__ void __launch_bounds__(256, 2)
gemm_tc(const float* __restrict__ A, const float* __restrict__ Bm,
        const float* __restrict__ bias, const float* __restrict__ skip,
        float* __restrict__ C, int M, int N, int K)
{
    extern __shared__ float sm[];
    float* As = sm;                 // [2][128][36]
    float* Bs = sm + 2 * GA_BUF;    // [2][32][136]

    const int tid = threadIdx.x;
    const int bm = blockIdx.y, bn = blockIdx.x;
    const int wid = tid >> 5, lane = tid & 31;
    const int wm = wid >> 2, wn = wid & 3;  // warp 64x32 tile
    const int lg = lane >> 2, lc = lane & 3;

    const float* Ag = A + (size_t)bm * 128 * K;
    const float* Bg = Bm + bn * 128;
    const int T = K / 32;

    #pragma unroll
    for (int it = 0; it < 4; it++) {
        int fid = it * 256 + tid;
        int r = fid >> 3, c4 = fid & 7;
        cp16(&As[r * GA_STRIDE + c4 * 4], Ag + (size_t)r * K + c4 * 4);
    }
    #pragma unroll
    for (int it = 0; it < 4; it++) {
        int fid = it * 256 + tid;
        int r = fid >> 5, c4 = fid & 31;
        cp16(&Bs[r * GB_STRIDE + c4 * 4], Bg + (size_t)r * N + c4 * 4);
    }
    CP_COMMIT();

    float acc[4][4][4] = {};

    for (int t = 0; t < T; t++) {
        const int cur = t & 1;
        if (t + 1 < T) {
            const int nb = cur ^ 1;
            const int k0 = (t + 1) * 32;
            #pragma unroll
            for (int it = 0; it < 4; it++) {
                int fid = it * 256 + tid;
                int r = fid >> 3, c4 = fid & 7;
                cp16(&As[nb * GA_BUF + r * GA_STRIDE + c4 * 4],
                     Ag + (size_t)r * K + k0 + c4 * 4);
            }
            #pragma unroll
            for (int it = 0; it < 4; it++) {
                int fid = it * 256 + tid;
                int r = fid >> 5, c4 = fid & 31;
                cp16(&Bs[nb * GB_BUF + r * GB_STRIDE + c4 * 4],
                     Bg + (size_t)(k0 + r) * N + c4 * 4);
            }
            CP_COMMIT();
            asm volatile("cp.async.wait_group 1;\n");
        } else {
            asm volatile("cp.async.wait_group 0;\n");
        }
        __syncthreads();

        const float* Ab = As + cur * GA_BUF;
        const float* Bb = Bs + cur * GB_BUF;

        #pragma unroll
        for (int ks = 0; ks < 4; ks++) {
            const int kA = ks * 8 + lc;
            unsigned a[4][4], b[4][2];
            #pragma unroll
            for (int mf = 0; mf < 4; mf++) {
                int m = wm * 64 + mf * 16 + lg;
                a[mf][0] = asu(Ab[m * GA_STRIDE + kA]);
                a[mf][1] = asu(Ab[(m + 8) * GA_STRIDE + kA]);
                a[mf][2] = asu(Ab[m * GA_STRIDE + kA + 4]);
                a[mf][3] = asu(Ab[(m + 8) * GA_STRIDE + kA + 4]);
            }
            #pragma unroll
            for (int nf = 0; nf < 4; nf++) {
                int n = wn * 32 + nf * 8 + lg;
                b[nf][0] = asu(Bb[kA * GB_STRIDE + n]);
                b[nf][1] = asu(Bb[(kA + 4) * GB_STRIDE + n]);
            }
            #pragma unroll
            for (int mf = 0; mf < 4; mf++)
                #pragma unroll
                for (int nf = 0; nf < 4; nf++)
                    mma_tf32(acc[mf][nf], a[mf], b[nf]);
        }
        __syncthreads();
    }

    #pragma unroll
    for (int mf = 0; mf < 4; mf++) {
        const size_t r0 = (size_t)bm * 128 + wm * 64 + mf * 16 + lg;
        #pragma unroll
        for (int nf = 0; nf < 4; nf++) {
            const int c = bn * 128 + wn * 32 + nf * 8 + lc * 2;
            const float b0 = bias[c], b1 = bias[c + 1];
            float v00 = swish_f(acc[mf][nf][0] + b0);
            float v01 = swish_f(acc[mf][nf][1] + b1);
            float v10 = swish_f(acc[mf][nf][2] + b0);
            float v11 = swish_f(acc[mf][nf][3] + b1);
            if (EPI == 1) {
                v00 += skip[r0 * (size_t)N + c];
                v01 += skip[r0 * (size_t)N + c + 1];
                v10 += skip[(r0 + 8) * (size_t)N + c];
                v11 += skip[(r0 + 8) * (size_t)N + c + 1];
            } else {
                v00 = rna_tf32(v00); v01 = rna_tf32(v01);
                v10 = rna_tf32(v10); v11 = rna_tf32(v11);
            }
            *(float2*)&C[r0 * (size_t)N + c] = make_float2(v00, v01);
            *(float2*)&C[(r0 + 8) * (size_t)N + c] = make_float2(v10, v11);
        }
    }
}

// ============================================================================
// FlashAttention-2 style: block = (qt 64 rows, h, b), 128 threads (4 warps),
// each warp owns 16 Q rows and the full 64-key tile. S and softmax entirely
// in registers. QK^T in tf32, P*V in bf16 (V pre-transposed by vtrans_kernel).
// K double-buffered via cp.async (fp32), V^T double-buffered (bf16).
// ============================================================================
#define ATK 68          // K smem row stride (floats)
#define ATV 72          // V^T smem row stride (bf16)
#define AK_BUF (64 * ATK)   // 4352 floats / buffer
#define AV_BUF (64 * ATV)   // 4608 bf16 / buffer
#define A_SMEM_BYTES (2 * AK_BUF * 4 + 2 * AV_BUF * 2)  // 34816 + 18432 = 53248

__global__ void __launch_bounds__(128, 3)
attn_fa(const float* __restrict__ qkv, const __nv_bfloat16* __restrict__ vt,
        float* __restrict__ nv)
{
    extern __shared__ char smraw[];
    float* Ks = (float*)smraw;
    __nv_bfloat16* Vs = (__nv_bfloat16*)(smraw + 2 * AK_BUF * 4);

    const int qt = blockIdx.x, h = blockIdx.y, b = blockIdx.z;
    const int tid = threadIdx.x, wid = tid >> 5, lane = tid & 31;
    const int lg = lane >> 2, lc = lane & 3;
    const size_t rowbase = (size_t)b * LL;
    const int hoff = h * (3 * HDIM);
    const float scale = 0.022097086912079608f;  // 1/sqrt(2048)

    const float* kbase = qkv + rowbase * QKVN + hoff + HDIM;
    const __nv_bfloat16* vtbase = vt + ((size_t)(b * NH + h) * HDIM) * LL;

    // prologue: K/V tile 0
    #pragma unroll
    for (int it = 0; it < 8; it++) {
        int fid = it * 128 + tid;
        int r = fid >> 4, c4 = fid & 15;
        cp16(&Ks[r * ATK + c4 * 4], kbase + (size_t)r * QKVN + c4 * 4);
    }
    #pragma unroll
    for (int it = 0; it < 4; it++) {
        int fid = it * 128 + tid;
        int d = fid >> 3, c8 = fid & 7;
        cp16(&Vs[d * ATV + c8 * 8], vtbase + (size_t)d * LL + c8 * 8);
    }
    CP_COMMIT();

    // Q fragments straight from gmem (tf32-rounded after scaling)
    unsigned qa[8][4];
    {
        const float* qbase = qkv + (rowbase + qt * 64 + wid * 16) * QKVN + hoff;
        #pragma unroll
        for (int ks = 0; ks < 8; ks++) {
            const int k = ks * 8 + lc;
            qa[ks][0] = asu(rna_tf32(qbase[(size_t)lg * QKVN + k] * scale));
            qa[ks][1] = asu(rna_tf32(qbase[(size_t)(lg + 8) * QKVN + k] * scale));
            qa[ks][2] = asu(rna_tf32(qbase[(size_t)lg * QKVN + k + 4] * scale));
            qa[ks][3] = asu(rna_tf32(qbase[(size_t)(lg + 8) * QKVN + k + 4] * scale));
        }
    }

    float o[8][4] = {};
    float m0 = -3.0e38f, m1 = -3.0e38f, l0 = 0.0f, l1 = 0.0f;

    for (int kt = 0; kt < LL / 64; kt++) {
        const int cur = kt & 1;
        if (kt + 1 < LL / 64) {
            const int nb = cur ^ 1;
            const float* kg = kbase + (size_t)(kt + 1) * 64 * QKVN;
            const __nv_bfloat16* vg = vtbase + (kt + 1) * 64;
            #pragma unroll
            for (int it = 0; it < 8; it++) {
                int fid = it * 128 + tid;
                int r = fid >> 4, c4 = fid & 15;
                cp16(&Ks[nb * AK_BUF + r * ATK + c4 * 4], kg + (size_t)r * QKVN + c4 * 4);
            }
            #pragma unroll
            for (int it = 0; it < 4; it++) {
                int fid = it * 128 + tid;
                int d = fid >> 3, c8 = fid & 7;
                cp16(&Vs[nb * AV_BUF + d * ATV + c8 * 8], vg + (size_t)d * LL + c8 * 8);
            }
            CP_COMMIT();
            asm volatile("cp.async.wait_group 1;\n");
        } else {
            asm volatile("cp.async.wait_group 0;\n");
        }
        __syncthreads();

        const float* Kb = Ks + cur * AK_BUF;
        const __nv_bfloat16* Vb = Vs + cur * AV_BUF;

        // S = Q K^T : 16x64 per warp, 8 n-fragments, tf32
        float s[8][4] = {};
        #pragma unroll
        for (int ks = 0; ks < 8; ks++) {
            const int kA = ks * 8 + lc;
            #pragma unroll
            for (int nf = 0; nf < 8; nf++) {
                const int n = nf * 8 + lg;
                unsigned bb[2];
                bb[0] = asu(Kb[n * ATK + kA]);
                bb[1] = asu(Kb[n * ATK + kA + 4]);
                mma_tf32(s[nf], qa[ks], bb);
            }
        }

        // in-register online softmax (rows lg -> m0/l0, lg+8 -> m1/l1)
        float mx0 = -3.0e38f, mx1 = -3.0e38f;
        #pragma unroll
        for (int nf = 0; nf < 8; nf++) {
            mx0 = fmaxf(mx0, fmaxf(s[nf][0], s[nf][1]));
            mx1 = fmaxf(mx1, fmaxf(s[nf][2], s[nf][3]));
        }
        mx0 = fmaxf(mx0, __shfl_xor_sync(0xffffffffu, mx0, 1));
        mx0 = fmaxf(mx0, __shfl_xor_sync(0xffffffffu, mx0, 2));
        mx1 = fmaxf(mx1, __shfl_xor_sync(0xffffffffu, mx1, 1));
        mx1 = fmaxf(mx1, __shfl_xor_sync(0xffffffffu, mx1, 2));
        const float mn0 = fmaxf(m0, mx0), mn1 = fmaxf(m1, mx1);
        const float al0 = __expf(m0 - mn0), al1 = __expf(m1 - mn1);
        m0 = mn0; m1 = mn1;

        float sum0 = 0.0f, sum1 = 0.0f;
        #pragma unroll
        for (int nf = 0; nf < 8; nf++) {
            s[nf][0] = __expf(s[nf][0] - mn0);
            s[nf][1] = __expf(s[nf][1] - mn0);
            s[nf][2] = __expf(s[nf][2] - mn1);
            s[nf][3] = __expf(s[nf][3] - mn1);
            sum0 += s[nf][0] + s[nf][1];
            sum1 += s[nf][2] + s[nf][3];
        }
        sum0 += __shfl_xor_sync(0xffffffffu, sum0, 1);
        sum0 += __shfl_xor_sync(0xffffffffu, sum0, 2);
        sum1 += __shfl_xor_sync(0xffffffffu, sum1, 1);
        sum1 += __shfl_xor_sync(0xffffffffu, sum1, 2);
        l0 = l0 * al0 + sum0;
        l1 = l1 * al1 + sum1;

        // rescale O
        #pragma unroll
        for (int nf = 0; nf < 8; nf++) {
            o[nf][0] *= al0; o[nf][1] *= al0;
            o[nf][2] *= al1; o[nf][3] *= al1;
        }

        // pack P -> bf16 A fragments (k16 steps t=0..3 over the 64 keys)
        unsigned pa[4][4];
        #pragma unroll
        for (int t = 0; t < 4; t++) {
            pa[t][0] = pack_bf16(s[2 * t][0], s[2 * t][1]);
            pa[t][1] = pack_bf16(s[2 * t][2], s[2 * t][3]);
            pa[t][2] = pack_bf16(s[2 * t + 1][0], s[2 * t + 1][1]);
            pa[t][3] = pack_bf16(s[2 * t + 1][2], s[2 * t + 1][3]);
        }

        // O += P V  (bf16 m16n8k16; B from transposed V: Vb[d][seq])
        #pragma unroll
        for (int t = 0; t < 4; t++) {
            #pragma unroll
            for (int nf = 0; nf < 8; nf++) {
                const int d = nf * 8 + lg;
                unsigned bb[2];
                bb[0] = *(const unsigned*)&Vb[d * ATV + t * 16 + 2 * lc];
                bb[1] = *(const unsigned*)&Vb[d * ATV + t * 16 + 2 * lc + 8];
                mma_bf16(o[nf], pa[t], bb);
            }
        }
        __syncthreads();
    }

    // epilogue: 1/l scaling, rna (feeds GEMM2 A operand), store
    {
        const float li0 = 1.0f / l0, li1 = 1.0f / l1;
        const size_t row0 = rowbase + qt * 64 + wid * 16 + lg;
        #pragma unroll
        for (int nf = 0; nf < 8; nf++) {
            const int c = h * HDIM + nf * 8 + 2 * lc;
            *(float2*)&nv[row0 * (size_t)(NH * HDIM) + c] =
                make_float2(rna_tf32(o[nf][0] * li0), rna_tf32(o[nf][1] * li0));
            *(float2*)&nv[(row0 + 8) * (size_t)(NH * HDIM) + c] =
                make_float2(rna_tf32(o[nf][2] * li1), rna_tf32(o[nf][3] * li1));
        }
    }
}

// ============================================================================
// LayerNorm over D=1024. One block (256 threads) per row.
// ============================================================================
__global__ void __launch_bounds__(256)
ln_kernel(const float* __restrict__ hb, float* __restrict__ out)
{
    const int row = blockIdx.x;
    const float4* p4 = (const float4*)(hb + (size_t)row * DD);
    float4 v = p4[threadIdx.x];
    float s  = v.x + v.y + v.z + v.w;
    float s2 = v.x * v.x + v.y * v.y + v.z * v.z + v.w * v.w;

    __shared__ float rs[8], rs2[8];
    const int wid = threadIdx.x >> 5, lane = threadIdx.x & 31;
    #pragma unroll
    for (int off = 16; off > 0; off >>= 1) {
        s  += __shfl_xor_sync(0xffffffffu, s, off);
        s2 += __shfl_xor_sync(0xffffffffu, s2, off);
    }
    if (lane == 0) { rs[wid] = s; rs2[wid] = s2; }
    __syncthreads();
    if (threadIdx.x == 0) {
        float a = 0.f, b2 = 0.f;
        #pragma unroll
        for (int i = 0; i < 8; i++) { a += rs[i]; b2 += rs2[i]; }
        rs[0] = a; rs2[0] = b2;
    }
    __syncthreads();
    const float mu = rs[0] * (1.0f / DD);
    const float var = rs2[0] * (1.0f / DD) - mu * mu;
    const float rstd = rsqrtf(var + 1e-5f);
    float4 ov = make_float4((v.x - mu) * rstd, (v.y - mu) * rstd,
                            (v.z - mu) * rstd, (v.w - mu) * rstd);
    ((float4*)(out + (size_t)row * DD))[threadIdx.x] = ov;
}

// ============================================================================
extern "C" void kernel_launch(void* const* d_in, const int* in_sizes, int n_in,
                              void* d_out, int out_size)
{
    const float* x     = (const float*)d_in[0];
    const float* W_fc  = (const float*)d_in[1];
    const float* b_fc  = (const float*)d_in[2];
    const float* W_fc2 = (const float*)d_in[3];
    const float* b_fc2 = (const float*)d_in[4];
    float* out = (float*)d_out;

    void* p;
    cudaGetSymbolAddress(&p, g_qkv);   float* qkv   = (float*)p;
    cudaGetSymbolAddress(&p, g_newv);  float* nv    = (float*)p;
    cudaGetSymbolAddress(&p, g_hbuf);  float* hb    = (float*)p;
    cudaGetSymbolAddress(&p, g_xr);    float* xr    = (float*)p;
    cudaGetSymbolAddress(&p, g_wfcr);  float* wfcr  = (float*)p;
    cudaGetSymbolAddress(&p, g_wfc2r); float* wfc2r = (float*)p;
    cudaGetSymbolAddress(&p, g_vt);    __nv_bfloat16* vt = (__nv_bfloat16*)p;

    // Pre-round GEMM operands to tf32 (rna) so HW mma sees exact tf32 values.
    {
        int n4x = NROWS * DD / 4;
        int n4w = DD * QKVN / 4;
        int n4w2 = NH * HDIM * DD / 4;
        round_kernel<<<n4x / 256, 256>>>(x, xr, n4x);
        round_kernel<<<n4w / 256, 256>>>(W_fc, wfcr, n4w);
        round_kernel<<<n4w2 / 256, 256>>>(W_fc2, wfc2r, n4w2);
    }

    const int g_smem = G_SMEM_FLOATS * 4;    // 71680
    cudaFuncSetAttribute(gemm_tc<0>, cudaFuncAttributeMaxDynamicSharedMemorySize, g_smem);
    cudaFuncSetAttribute(gemm_tc<1>, cudaFuncAttributeMaxDynamicSharedMemorySize, g_smem);

    // GEMM1: qkv = rna(swish(x @ W_fc + b_fc))
    dim3 g1(QKVN / 128, NROWS / 128);
    gemm_tc<0><<<g1, 256, g_smem>>>(xr, wfcr, b_fc, nullptr, qkv, NROWS, QKVN, DD);

    // V^T bf16 for the PV mma
    dim3 gv(LL / 64, NH, BB);
    vtrans_kernel<<<gv, 256>>>(qkv, vt);

    // FlashAttention-2
    cudaFuncSetAttribute(attn_fa, cudaFuncAttributeMaxDynamicSharedMemorySize, A_SMEM_BYTES);
    dim3 ga(LL / 64, NH, BB);
    attn_fa<<<ga, 128, A_SMEM_BYTES>>>(qkv, vt, nv);

    // GEMM2: hb = x + swish(nv @ W_fc2 + b_fc2)
    dim3 g2(DD / 128, NROWS / 128);
    gemm_tc<1><<<g2, 256, g_smem>>>(nv, wfc2r, b_fc2, x, hb, NROWS, DD, DD);

    // LayerNorm -> out
    ln_kernel<<<NROWS, 256>>>(hb, out);
}

// round 11
// speedup vs baseline: 7.4219x; 1.5266x over previous
#include <cuda_runtime.h>
#include <cuda_bf16.h>

#define BB 4
#define LL 2048
#define DD 1024
#define NH 16
#define HDIM 64
#define QKVN (NH * HDIM * 3)   // 3072
#define NROWS (BB * LL)        // 8192

// ---- scratch (static device globals; no dynamic allocation) ----
__device__ __nv_bfloat16 g_qkvb[(size_t)NROWS * QKVN];        // 48 MB
__device__ __nv_bfloat16 g_nvb[(size_t)NROWS * (NH * HDIM)];  // 16 MB
__device__ float         g_hbuf[(size_t)NROWS * DD];          // 32 MB
__device__ __nv_bfloat16 g_xb[(size_t)NROWS * DD];            // 16 MB
__device__ __nv_bfloat16 g_wbT[(size_t)QKVN * DD];            //  6 MB (W_fc^T)
__device__ __nv_bfloat16 g_w2bT[(size_t)DD * (NH * HDIM)];    //  2 MB (W_fc2^T)
__device__ __nv_bfloat16 g_vt[(size_t)BB * NH * HDIM * LL];   // 16 MB (V^T [b][h][d][seq])

__device__ __forceinline__ float swish_f(float v) {
    return v * (1.0f / (1.0f + __expf(-v)));
}

__device__ __forceinline__ unsigned pack_bf16(float lo, float hi) {
    unsigned r;
    asm("cvt.rn.bf16x2.f32 %0, %1, %2;" : "=r"(r) : "f"(hi), "f"(lo));
    return r;
}

__device__ __forceinline__ void cp16(void* dst, const void* src) {
    unsigned s = (unsigned)__cvta_generic_to_shared(dst);
    asm volatile("cp.async.cg.shared.global [%0], [%1], 16;\n" :: "r"(s), "l"(src));
}
#define CP_COMMIT() asm volatile("cp.async.commit_group;\n")

// m16n8k16 bf16 mma, accumulate in place.
__device__ __forceinline__ void mma_bf16(float c[4], const unsigned a[4],
                                         const unsigned b[2]) {
    asm volatile(
        "mma.sync.aligned.m16n8k16.row.col.f32.bf16.bf16.f32 "
        "{%0,%1,%2,%3}, {%4,%5,%6,%7}, {%8,%9}, {%0,%1,%2,%3};\n"
        : "+f"(c[0]), "+f"(c[1]), "+f"(c[2]), "+f"(c[3])
        : "r"(a[0]), "r"(a[1]), "r"(a[2]), "r"(a[3]), "r"(b[0]), "r"(b[1]));
}

// ============================================================================
// f32 -> bf16 elementwise convert.
// ============================================================================
__global__ void __launch_bounds__(256)
cvt_kernel(const float* __restrict__ in, __nv_bfloat16* __restrict__ out, int n4)
{
    int i = blockIdx.x * blockDim.x + threadIdx.x;
    if (i < n4) {
        float4 v = ((const float4*)in)[i];
        uint2 o;
        o.x = pack_bf16(v.x, v.y);
        o.y = pack_bf16(v.z, v.w);
        ((uint2*)out)[i] = o;
    }
}

// ============================================================================
// Transpose + convert: w [K][N] f32 -> wt [N][K] bf16. 64x64 tiles, 256 thr.
// ============================================================================
__global__ void __launch_bounds__(256)
transcvt_kernel(const float* __restrict__ w, __nv_bfloat16* __restrict__ wt,
                int K, int N)
{
    __shared__ float ts[64][65];
    const int n0 = blockIdx.x * 64, k0 = blockIdx.y * 64;
    const int tid = threadIdx.x;

    #pragma unroll
    for (int it = 0; it < 4; it++) {
        int fid = it * 256 + tid;
        int r = fid >> 4, c4 = (fid & 15) << 2;
        float4 v = *(const float4*)(w + (size_t)(k0 + r) * N + n0 + c4);
        ts[r][c4] = v.x; ts[r][c4 + 1] = v.y; ts[r][c4 + 2] = v.z; ts[r][c4 + 3] = v.w;
    }
    __syncthreads();

    #pragma unroll
    for (int it = 0; it < 8; it++) {
        int fid = it * 256 + tid;
        int nl = fid >> 5, j = fid & 31;
        unsigned pk = pack_bf16(ts[2 * j][nl], ts[2 * j + 1][nl]);
        *(unsigned*)(wt + (size_t)(n0 + nl) * K + k0 + 2 * j) = pk;
    }
}

// ============================================================================
// V^T transpose: qkvb V slice [seq][d] bf16 -> vt [b][h][d][seq] bf16.
// ============================================================================
__global__ void __launch_bounds__(256)
vtrans_kernel(const __nv_bfloat16* __restrict__ qkvb, __nv_bfloat16* __restrict__ vt)
{
    __shared__ __nv_bfloat16 ts[64][72];
    const int st = blockIdx.x, h = blockIdx.y, b = blockIdx.z;
    const int tid = threadIdx.x;
    const __nv_bfloat16* src = qkvb + ((size_t)b * LL + st * 64) * QKVN
                               + h * (3 * HDIM) + 2 * HDIM;

    #pragma unroll
    for (int it = 0; it < 8; it++) {
        int fid = it * 256 + tid;
        int r = fid >> 5, j = fid & 31;
        *(unsigned*)&ts[r][2 * j] = *(const unsigned*)(src + (size_t)r * QKVN + 2 * j);
    }
    __syncthreads();

    const size_t obase = ((size_t)(b * NH + h) * HDIM) * LL + st * 64;
    #pragma unroll
    for (int it = 0; it < 8; it++) {
        int fid = it * 256 + tid;
        int d = fid >> 5, j = fid & 31;
        __nv_bfloat162 p;
        p.x = ts[2 * j][d];
        p.y = ts[2 * j + 1][d];
        *(__nv_bfloat162*)(vt + obase + (size_t)d * LL + 2 * j) = p;
    }
}

// ============================================================================
// BF16 tensor-core GEMM: block 128x128, ktile 64, 256 threads (8 warps 2x4,
// warp tile 64x32), m16n8k16, fp32 accum. A [M][K] bf16 row-major,
// BT [N][K] bf16 row-major (pre-transposed weights). Double-buffered cp.async.
// EPI=0: C(bf16) = bf16(swish(A*B + bias))
// EPI=1: C(f32)  = skip + swish(A*B + bias)
// ============================================================================
#define GSTR 72                 // bf16 per smem row (64 + 8 pad); 36 b32
#define GBUF (128 * GSTR)       // 9216 bf16 = 18432 B per stage per operand
#define G_SMEM_BYTES (4 * GBUF * 2)   // 73728

template <int EPI>
__global__ void __launch_bounds__(256, 2)
gemm_bf(const __nv_bfloat16* __restrict__ A, const __nv_bfloat16* __restrict__ BT,
        const float* __restrict__ bias, const float* __restrict__ skip,
        void* __restrict__ Cout, int M, int N, int K)
{
    extern __shared__ __nv_bfloat16 smb[];
    __nv_bfloat16* As = smb;                // [2][128][72]
    __nv_bfloat16* Bs = smb + 2 * GBUF;     // [2][128][72]

    const int tid = threadIdx.x;
    const int bm = blockIdx.y, bn = blockIdx.x;
    const int wid = tid >> 5, lane = tid & 31;
    const int wm = wid >> 2, wn = wid & 3;  // warp 64x32 tile
    const int lg = lane >> 2, lc = lane & 3;

    const __nv_bfloat16* Ag = A + (size_t)bm * 128 * K;
    const __nv_bfloat16* Bg = BT + (size_t)bn * 128 * K;
    const int T = K / 64;

    #pragma unroll
    for (int it = 0; it < 4; it++) {
        int fid = it * 256 + tid;
        int r = fid >> 3, c = fid & 7;
        cp16(&As[r * GSTR + c * 8], Ag + (size_t)r * K + c * 8);
        cp16(&Bs[r * GSTR + c * 8], Bg + (size_t)r * K + c * 8);
    }
    CP_COMMIT();

    float acc[4][4][4] = {};

    for (int t = 0; t < T; t++) {
        const int cur = t & 1;
        if (t + 1 < T) {
            const int nb = cur ^ 1;
            const int k0 = (t + 1) * 64;
            #pragma unroll
            for (int it = 0; it < 4; it++) {
                int fid = it * 256 + tid;
                int r = fid >> 3, c = fid & 7;
                cp16(&As[nb * GBUF + r * GSTR + c * 8], Ag + (size_t)r * K + k0 + c * 8);
                cp16(&Bs[nb * GBUF + r * GSTR + c * 8], Bg + (size_t)r * K + k0 + c * 8);
            }
            CP_COMMIT();
            asm volatile("cp.async.wait_group 1;\n");
        } else {
            asm volatile("cp.async.wait_group 0;\n");
        }
        __syncthreads();

        const unsigned* Ab = (const unsigned*)(As + cur * GBUF);
        const unsigned* Bb = (const unsigned*)(Bs + cur * GBUF);

        #pragma unroll
        for (int step = 0; step < 4; step++) {
            const int base = step * 8 + lc;
            unsigned a[4][4], b[4][2];
            #pragma unroll
            for (int mf = 0; mf < 4; mf++) {
                const int m = wm * 64 + mf * 16 + lg;
                a[mf][0] = Ab[m * 36 + base];
                a[mf][1] = Ab[(m + 8) * 36 + base];
                a[mf][2] = Ab[m * 36 + base + 4];
                a[mf][3] = Ab[(m + 8) * 36 + base + 4];
            }
            #pragma unroll
            for (int nf = 0; nf < 4; nf++) {
                const int n = wn * 32 + nf * 8 + lg;
                b[nf][0] = Bb[n * 36 + base];
                b[nf][1] = Bb[n * 36 + base + 4];
            }
            #pragma unroll
            for (int mf = 0; mf < 4; mf++)
                #pragma unroll
                for (int nf = 0; nf < 4; nf++)
                    mma_bf16(acc[mf][nf], a[mf], b[nf]);
        }
        __syncthreads();
    }

    // epilogue
    #pragma unroll
    for (int mf = 0; mf < 4; mf++) {
        const size_t r0 = (size_t)bm * 128 + wm * 64 + mf * 16 + lg;
        #pragma unroll
        for (int nf = 0; nf < 4; nf++) {
            const int c = bn * 128 + wn * 32 + nf * 8 + lc * 2;
            const float b0 = bias[c], b1 = bias[c + 1];
            float v00 = swish_f(acc[mf][nf][0] + b0);
            float v01 = swish_f(acc[mf][nf][1] + b1);
            float v10 = swish_f(acc[mf][nf][2] + b0);
            float v11 = swish_f(acc[mf][nf][3] + b1);
            if (EPI == 1) {
                float* C = (float*)Cout;
                v00 += skip[r0 * (size_t)N + c];
                v01 += skip[r0 * (size_t)N + c + 1];
                v10 += skip[(r0 + 8) * (size_t)N + c];
                v11 += skip[(r0 + 8) * (size_t)N + c + 1];
                *(float2*)&C[r0 * (size_t)N + c] = make_float2(v00, v01);
                *(float2*)&C[(r0 + 8) * (size_t)N + c] = make_float2(v10, v11);
            } else {
                __nv_bfloat16* C = (__nv_bfloat16*)Cout;
                *(unsigned*)&C[r0 * (size_t)N + c] = pack_bf16(v00, v01);
                *(unsigned*)&C[(r0 + 8) * (size_t)N + c] = pack_bf16(v10, v11);
            }
        }
    }
}

// ============================================================================
// FlashAttention-2, all-bf16 operands: block = (qt 64 rows, h, b), 128 thr
// (4 warps), each warp owns 16 Q rows x full 64-key tile. QK^T and P*V both
// m16n8k16 bf16, fp32 accum; softmax in registers. K and V^T double-buffered.
// Softmax scale applied to S post-mma.
// ============================================================================
#define ATK 72              // K smem row stride (bf16); 36 b32
#define ATV 72              // V^T smem row stride (bf16)
#define AK_BUF (64 * ATK)   // 4608 bf16 / buffer
#define AV_BUF (64 * ATV)   // 4608 bf16 / buffer
#define A_SMEM_BYTES (2 * AK_BUF * 2 + 2 * AV_BUF * 2)  // 36864

__global__ void __launch_bounds__(128, 4)
attn_fa(const __nv_bfloat16* __restrict__ qkvb, const __nv_bfloat16* __restrict__ vt,
        __nv_bfloat16* __restrict__ nvb)
{
    extern __shared__ char smraw[];
    __nv_bfloat16* Ks = (__nv_bfloat16*)smraw;
    __nv_bfloat16* Vs = (__nv_bfloat16*)(smraw + 2 * AK_BUF * 2);

    const int qt = blockIdx.x, h = blockIdx.y, b = blockIdx.z;
    const int tid = threadIdx.x, wid = tid >> 5, lane = tid & 31;
    const int lg = lane >> 2, lc = lane & 3;
    const size_t rowbase = (size_t)b * LL;
    const int hoff = h * (3 * HDIM);
    const float scale = 0.022097086912079608f;  // 1/sqrt(2048)

    const __nv_bfloat16* kbase = qkvb + rowbase * QKVN + hoff + HDIM;
    const __nv_bfloat16* vtbase = vt + ((size_t)(b * NH + h) * HDIM) * LL;

    // prologue: K/V tile 0 (64 rows x 64 bf16 = 8 cp16 per row)
    #pragma unroll
    for (int it = 0; it < 4; it++) {
        int fid = it * 128 + tid;
        int r = fid >> 3, c = fid & 7;
        cp16(&Ks[r * ATK + c * 8], kbase + (size_t)r * QKVN + c * 8);
        cp16(&Vs[r * ATV + c * 8], vtbase + (size_t)r * LL + c * 8);
    }
    CP_COMMIT();

    // Q fragments straight from gmem (bf16, 4 k16-steps over d=64)
    unsigned qa[4][4];
    {
        const __nv_bfloat16* qb = qkvb + (rowbase + qt * 64 + wid * 16) * QKVN + hoff;
        #pragma unroll
        for (int st = 0; st < 4; st++) {
            qa[st][0] = *(const unsigned*)(qb + (size_t)lg * QKVN + st * 16 + 2 * lc);
            qa[st][1] = *(const unsigned*)(qb + (size_t)(lg + 8) * QKVN + st * 16 + 2 * lc);
            qa[st][2] = *(const unsigned*)(qb + (size_t)lg * QKVN + st * 16 + 8 + 2 * lc);
            qa[st][3] = *(const unsigned*)(qb + (size_t)(lg + 8) * QKVN + st * 16 + 8 + 2 * lc);
        }
    }

    float o[8][4] = {};
    float m0 = -3.0e38f, m1 = -3.0e38f, l0 = 0.0f, l1 = 0.0f;

    for (int kt = 0; kt < LL / 64; kt++) {
        const int cur = kt & 1;
        if (kt + 1 < LL / 64) {
            const int nb = cur ^ 1;
            const __nv_bfloat16* kg = kbase + (size_t)(kt + 1) * 64 * QKVN;
            const __nv_bfloat16* vg = vtbase + (kt + 1) * 64;
            #pragma unroll
            for (int it = 0; it < 4; it++) {
                int fid = it * 128 + tid;
                int r = fid >> 3, c = fid & 7;
                cp16(&Ks[nb * AK_BUF + r * ATK + c * 8], kg + (size_t)r * QKVN + c * 8);
                cp16(&Vs[nb * AV_BUF + r * ATV + c * 8], vg + (size_t)r * LL + c * 8);
            }
            CP_COMMIT();
            asm volatile("cp.async.wait_group 1;\n");
        } else {
            asm volatile("cp.async.wait_group 0;\n");
        }
        __syncthreads();

        const unsigned* Kb = (const unsigned*)(Ks + cur * AK_BUF);
        const __nv_bfloat16* Vb = Vs + cur * AV_BUF;

        // S = Q K^T : 16x64 per warp, bf16 k16 x 4 steps
        float s[8][4] = {};
        #pragma unroll
        for (int st = 0; st < 4; st++) {
            const int base = st * 8 + lc;
            #pragma unroll
            for (int nf = 0; nf < 8; nf++) {
                const int n = nf * 8 + lg;
                unsigned bb[2];
                bb[0] = Kb[n * 36 + base];
                bb[1] = Kb[n * 36 + base + 4];
                mma_bf16(s[nf], qa[st], bb);
            }
        }
        // apply softmax scale
        #pragma unroll
        for (int nf = 0; nf < 8; nf++) {
            s[nf][0] *= scale; s[nf][1] *= scale;
            s[nf][2] *= scale; s[nf][3] *= scale;
        }

        // in-register online softmax (rows lg -> m0/l0, lg+8 -> m1/l1)
        float mx0 = -3.0e38f, mx1 = -3.0e38f;
        #pragma unroll
        for (int nf = 0; nf < 8; nf++) {
            mx0 = fmaxf(mx0, fmaxf(s[nf][0], s[nf][1]));
            mx1 = fmaxf(mx1, fmaxf(s[nf][2], s[nf][3]));
        }
        mx0 = fmaxf(mx0, __shfl_xor_sync(0xffffffffu, mx0, 1));
        mx0 = fmaxf(mx0, __shfl_xor_sync(0xffffffffu, mx0, 2));
        mx1 = fmaxf(mx1, __shfl_xor_sync(0xffffffffu, mx1, 1));
        mx1 = fmaxf(mx1, __shfl_xor_sync(0xffffffffu, mx1, 2));
        const float mn0 = fmaxf(m0, mx0), mn1 = fmaxf(m1, mx1);
        const float al0 = __expf(m0 - mn0), al1 = __expf(m1 - mn1);
        m0 = mn0; m1 = mn1;

        float sum0 = 0.0f, sum1 = 0.0f;
        #pragma unroll
        for (int nf = 0; nf < 8; nf++) {
            s[nf][0] = __expf(s[nf][0] - mn0);
            s[nf][1] = __expf(s[nf][1] - mn0);
            s[nf][2] = __expf(s[nf][2] - mn1);
            s[nf][3] = __expf(s[nf][3] - mn1);
            sum0 += s[nf][0] + s[nf][1];
            sum1 += s[nf][2] + s[nf][3];
        }
        sum0 += __shfl_xor_sync(0xffffffffu, sum0, 1);
        sum0 += __shfl_xor_sync(0xffffffffu, sum0, 2);
        sum1 += __shfl_xor_sync(0xffffffffu, sum1, 1);
        sum1 += __shfl_xor_sync(0xffffffffu, sum1, 2);
        l0 = l0 * al0 + sum0;
        l1 = l1 * al1 + sum1;

        // rescale O
        #pragma unroll
        for (int nf = 0; nf < 8; nf++) {
            o[nf][0] *= al0; o[nf][1] *= al0;
            o[nf][2] *= al1; o[nf][3] *= al1;
        }

        // pack P -> bf16 A fragments (k16 steps t over the 64 keys)
        unsigned pa[4][4];
        #pragma unroll
        for (int t = 0; t < 4; t++) {
            pa[t][0] = pack_bf16(s[2 * t][0], s[2 * t][1]);
            pa[t][1] = pack_bf16(s[2 * t][2], s[2 * t][3]);
            pa[t][2] = pack_bf16(s[2 * t + 1][0], s[2 * t + 1][1]);
            pa[t][3] = pack_bf16(s[2 * t + 1][2], s[2 * t + 1][3]);
        }

        // O += P V  (bf16 m16n8k16; B from transposed V: Vb[d][seq])
        #pragma unroll
        for (int t = 0; t < 4; t++) {
            #pragma unroll
            for (int nf = 0; nf < 8; nf++) {
                const int d = nf * 8 + lg;
                unsigned bb[2];
                bb[0] = *(const unsigned*)&Vb[d * ATV + t * 16 + 2 * lc];
                bb[1] = *(const unsigned*)&Vb[d * ATV + t * 16 + 2 * lc + 8];
                mma_bf16(o[nf], pa[t], bb);
            }
        }
        __syncthreads();
    }

    // epilogue: 1/l scaling, write bf16 (feeds GEMM2 A operand)
    {
        const float li0 = 1.0f / l0, li1 = 1.0f / l1;
        const size_t row0 = rowbase + qt * 64 + wid * 16 + lg;
        #pragma unroll
        for (int nf = 0; nf < 8; nf++) {
            const int c = h * HDIM + nf * 8 + 2 * lc;
            *(unsigned*)&nvb[row0 * (size_t)(NH * HDIM) + c] =
                pack_bf16(o[nf][0] * li0, o[nf][1] * li0);
            *(unsigned*)&nvb[(row0 + 8) * (size_t)(NH * HDIM) + c] =
                pack_bf16(o[nf][2] * li1, o[nf][3] * li1);
        }
    }
}

// ============================================================================
// LayerNorm over D=1024. One block (256 threads) per row.
// ============================================================================
__global__ void __launch_bounds__(256)
ln_kernel(const float* __restrict__ hb, float* __restrict__ out)
{
    const int row = blockIdx.x;
    const float4* p4 = (const float4*)(hb + (size_t)row * DD);
    float4 v = p4[threadIdx.x];
    float s  = v.x + v.y + v.z + v.w;
    float s2 = v.x * v.x + v.y * v.y + v.z * v.z + v.w * v.w;

    __shared__ float rs[8], rs2[8];
    const int wid = threadIdx.x >> 5, lane = threadIdx.x & 31;
    #pragma unroll
    for (int off = 16; off > 0; off >>= 1) {
        s  += __shfl_xor_sync(0xffffffffu, s, off);
        s2 += __shfl_xor_sync(0xffffffffu, s2, off);
    }
    if (lane == 0) { rs[wid] = s; rs2[wid] = s2; }
    __syncthreads();
    if (threadIdx.x == 0) {
        float a = 0.f, b2 = 0.f;
        #pragma unroll
        for (int i = 0; i < 8; i++) { a += rs[i]; b2 += rs2[i]; }
        rs[0] = a; rs2[0] = b2;
    }
    __syncthreads();
    const float mu = rs[0] * (1.0f / DD);
    const float var = rs2[0] * (1.0f / DD) - mu * mu;
    const float rstd = rsqrtf(var + 1e-5f);
    float4 ov = make_float4((v.x - mu) * rstd, (v.y - mu) * rstd,
                            (v.z - mu) * rstd, (v.w - mu) * rstd);
    ((float4*)(out + (size_t)row * DD))[threadIdx.x] = ov;
}

// ============================================================================
extern "C" void kernel_launch(void* const* d_in, const int* in_sizes, int n_in,
                              void* d_out, int out_size)
{
    const float* x     = (const float*)d_in[0];
    const float* W_fc  = (const float*)d_in[1];
    const float* b_fc  = (const float*)d_in[2];
    const float* W_fc2 = (const float*)d_in[3];
    const float* b_fc2 = (const float*)d_in[4];
    float* out = (float*)d_out;

    void* p;
    cudaGetSymbolAddress(&p, g_qkvb);  __nv_bfloat16* qkvb = (__nv_bfloat16*)p;
    cudaGetSymbolAddress(&p, g_nvb);   __nv_bfloat16* nvb  = (__nv_bfloat16*)p;
    cudaGetSymbolAddress(&p, g_hbuf);  float* hb = (float*)p;
    cudaGetSymbolAddress(&p, g_xb);    __nv_bfloat16* xb   = (__nv_bfloat16*)p;
    cudaGetSymbolAddress(&p, g_wbT);   __nv_bfloat16* wbT  = (__nv_bfloat16*)p;
    cudaGetSymbolAddress(&p, g_w2bT);  __nv_bfloat16* w2bT = (__nv_bfloat16*)p;
    cudaGetSymbolAddress(&p, g_vt);    __nv_bfloat16* vt   = (__nv_bfloat16*)p;

    // Convert x -> bf16; transpose+convert weights -> [N][K] bf16.
    cvt_kernel<<<(NROWS * DD / 4) / 256, 256>>>(x, xb, NROWS * DD / 4);
    {
        dim3 gw(QKVN / 64, DD / 64);
        transcvt_kernel<<<gw, 256>>>(W_fc, wbT, DD, QKVN);
        dim3 gw2(DD / 64, (NH * HDIM) / 64);
        transcvt_kernel<<<gw2, 256>>>(W_fc2, w2bT, NH * HDIM, DD);
    }

    cudaFuncSetAttribute(gemm_bf<0>, cudaFuncAttributeMaxDynamicSharedMemorySize, G_SMEM_BYTES);
    cudaFuncSetAttribute(gemm_bf<1>, cudaFuncAttributeMaxDynamicSharedMemorySize, G_SMEM_BYTES);

    // GEMM1: qkvb = bf16(swish(x @ W_fc + b_fc))
    dim3 g1(QKVN / 128, NROWS / 128);
    gemm_bf<0><<<g1, 256, G_SMEM_BYTES>>>(xb, wbT, b_fc, nullptr, qkvb, NROWS, QKVN, DD);

    // V^T for the PV mma
    dim3 gv(LL / 64, NH, BB);
    vtrans_kernel<<<gv, 256>>>(qkvb, vt);

    // FlashAttention-2 (all bf16 operands)
    cudaFuncSetAttribute(attn_fa, cudaFuncAttributeMaxDynamicSharedMemorySize, A_SMEM_BYTES);
    dim3 ga(LL / 64, NH, BB);
    attn_fa<<<ga, 128, A_SMEM_BYTES>>>(qkvb, vt, nvb);

    // GEMM2: hb = x + swish(nv @ W_fc2 + b_fc2)
    dim3 g2(DD / 128, NROWS / 128);
    gemm_bf<1><<<g2, 256, G_SMEM_BYTES>>>(nvb, w2bT, b_fc2, x, hb, NROWS, DD, DD);

    // LayerNorm -> out
    ln_kernel<<<NROWS, 256>>>(hb, out);
}